// round 6
// baseline (speedup 1.0000x reference)
#include <cuda_runtime.h>
#include <cuda_bf16.h>

#define NG 10000
#define W 256
#define H 256
#define TS 16
#define TX 16
#define TY 16
#define SEGS 8
#define SEGN (NG / SEGS)   // 1250
#define CAP  SEGN
#define ZSPLIT 4

// Static device scratch (no dynamic allocation anywhere)
static __device__ float4 g_parA[NG];                    // cx, cy, ha*log2e, b*log2e
static __device__ float4 g_parB[NG];                    // hc*log2e, log2(op), colR, colG
static __device__ float  g_parC[NG];                    // colB
static __device__ int    g_rng[NG];                     // tx0|tx1<<4|ty0<<8|ty1<<12
static __device__ int    g_tlist[TY * TX * SEGS * CAP]; // gid lists per (tile,seg)
static __device__ int    g_tcnt[TY * TX * SEGS];
static __device__ float  g_part[ZSPLIT][3 * H * W];

// fast tanh: 1 - 2/(1 + exp2(2x*log2e));  ~1e-6 abs err, no branches
__device__ __forceinline__ float fast_tanh(float x) {
    float e;
    asm("ex2.approx.f32 %0, %1;" : "=f"(e) : "f"(x * 2.885390081777927f)); // 2*log2e
    float r;
    asm("rcp.approx.f32 %0, %1;" : "=f"(r) : "f"(1.0f + e));
    return 1.0f - 2.0f * r;
}

// Prep: one thread per gaussian, 64-thread blocks (157 blocks -> all SMs).
__global__ __launch_bounds__(64) void prep_kernel(
    const float* __restrict__ xyz,
    const float* __restrict__ chol,
    const float* __restrict__ colors,
    const float* __restrict__ opacity) {
    int i = blockIdx.x * 64 + threadIdx.x;
    if (i >= NG) return;
    const float LOG2E = 1.4426950408889634f;
    float cx = 0.5f * W * (fast_tanh(xyz[2 * i]) + 1.0f);
    float cy = 0.5f * H * (fast_tanh(xyz[2 * i + 1]) + 1.0f);
    float L0 = chol[3 * i] + 0.5f;
    float L1 = chol[3 * i + 1];
    float L2 = chol[3 * i + 2] + 0.5f;
    float cxx = L0 * L0;
    float cxy = L0 * L1;
    float cyy = L1 * L1 + L2 * L2;
    float det = cxx * cyy - cxy * cxy;
    float inv = 1.0f / det;
    float op = opacity[i];
    float T = __logf(255.0f * op) + 0.05f;

    int tx0 = 15, tx1 = 0, ty0 = 15, ty1 = 0;  // empty
    if (det > 0.0f && op > 0.0f && T > 0.0f) {
        float rx = sqrtf(2.0f * T * cxx) + 1.0f;
        float ry = sqrtf(2.0f * T * cyy) + 1.0f;
        float xlo = cx - rx, xhi = cx + rx;
        float ylo = cy - ry, yhi = cy + ry;
        if (xhi >= 0.0f && xlo <= (float)(W - 1) &&
            yhi >= 0.0f && ylo <= (float)(H - 1)) {
            tx0 = max(0, (int)floorf(xlo * (1.0f / TS)));
            tx1 = min(TX - 1, (int)floorf(xhi * (1.0f / TS)));
            ty0 = max(0, (int)floorf(ylo * (1.0f / TS)));
            ty1 = min(TY - 1, (int)floorf(yhi * (1.0f / TS)));
        }
    }
    g_rng[i]  = tx0 | (tx1 << 4) | (ty0 << 8) | (ty1 << 12);
    g_parA[i] = make_float4(cx, cy, 0.5f * cyy * inv * LOG2E, -cxy * inv * LOG2E);
    g_parB[i] = make_float4(0.5f * cxx * inv * LOG2E, __log2f(op),
                            colors[3 * i], colors[3 * i + 1]);
    g_parC[i] = colors[3 * i + 2];
}

// Binning: reads only g_rng. Grid (SEGS, TY). Deterministic 16-ballot scan
// scatters gids (ascending) into the row's 16 per-tile lists.
__global__ __launch_bounds__(256) void bin_kernel() {
    const int seg = blockIdx.x, row = blockIdx.y;
    const int tid = threadIdx.x, lane = tid & 31, wid = tid >> 5;
    __shared__ unsigned sball[TX][9];
    __shared__ int sbase[TX];
    const int segBase = seg * SEGN;
    const unsigned lmask = (1u << lane) - 1u;

    if (tid < TX) sbase[tid] = 0;
    __syncthreads();

    for (int it = 0; it < (SEGN + 255) / 256; it++) {
        int i = segBase + it * 256 + tid;
        int rng = (i < segBase + SEGN) ? g_rng[i] : 0x0F00;
        int ty0 = (rng >> 8) & 15, ty1 = (rng >> 12) & 15;
        int t0 = rng & 15, t1 = (rng >> 4) & 15;
        bool pass = (ty0 <= row) && (row <= ty1);
        #pragma unroll
        for (int tx = 0; tx < TX; tx++) {
            unsigned b = __ballot_sync(0xffffffffu, pass && (t0 <= tx) && (tx <= t1));
            if (lane == 0) sball[tx][wid] = b;
        }
        __syncthreads();
        if (pass) {
            for (int tx = t0; tx <= t1; tx++) {
                int pos = sbase[tx];
                #pragma unroll
                for (int k = 0; k < 8; k++)
                    if (k < wid) pos += __popc(sball[tx][k]);
                pos += __popc(sball[tx][wid] & lmask);
                g_tlist[((row * TX + tx) * SEGS + seg) * CAP + pos] = i;
            }
        }
        __syncthreads();
        if (tid < TX) {
            int s = 0;
            #pragma unroll
            for (int k = 0; k < 8; k++) s += __popc(sball[tid][k]);
            sbase[tid] += s;
        }
        __syncthreads();
    }
    if (tid < TX) g_tcnt[(row * TX + tid) * SEGS + seg] = sbase[tid];
}

// Dense render: grid (TX, TY, ZSPLIT); each z handles SEGS/ZSPLIT segments.
__global__ __launch_bounds__(256) void render_kernel() {
    __shared__ float4 sA[256];
    __shared__ float4 sB[256];
    __shared__ float  sC[256];

    const int tid = threadIdx.x;
    const int bx = blockIdx.x, row = blockIdx.y, z = blockIdx.z;
    const int px = bx * TS + (tid & 15), py = row * TS + (tid >> 4);
    const float fpx = (float)px, fpy = (float)py;
    const int tileIdx = row * TX + bx;

    float accR = 0.0f, accG = 0.0f, accB = 0.0f;
    const int seg0 = z * (SEGS / ZSPLIT);

    for (int s = 0; s < SEGS / ZSPLIT; s++) {
        const int seg = seg0 + s;
        const int cnt = g_tcnt[tileIdx * SEGS + seg];
        const int* lst = g_tlist + (tileIdx * SEGS + seg) * CAP;
        for (int base = 0; base < cnt; base += 256) {
            int i = base + tid;
            if (i < cnt) {
                int g = lst[i];
                sA[tid] = g_parA[g];
                sB[tid] = g_parB[g];
                sC[tid] = g_parC[g];
            }
            __syncthreads();
            int m = min(256, cnt - base);
            #pragma unroll 2
            for (int j = 0; j < m; j++) {
                float4 A = sA[j];
                float4 B = sB[j];
                float dx = A.x - fpx;
                float dy = A.y - fpy;
                float sig = fmaf(A.z * dx, dx, fmaf(B.x * dy, dy, A.w * (dx * dy)));
                float k2 = B.y - sig;
                float alpha;
                asm("ex2.approx.f32 %0, %1;" : "=f"(alpha) : "f"(k2));
                float wgt = ((sig >= 0.0f) && (alpha >= (1.0f / 255.0f)))
                                ? fminf(alpha, 0.999f) : 0.0f;
                accR = fmaf(wgt, B.z, accR);
                accG = fmaf(wgt, B.w, accG);
                accB = fmaf(wgt, sC[j], accB);
            }
            __syncthreads();
        }
    }

    int idx = py * W + px;
    g_part[z][0 * (H * W) + idx] = accR;
    g_part[z][1 * (H * W) + idx] = accG;
    g_part[z][2 * (H * W) + idx] = accB;
}

__global__ __launch_bounds__(256) void finish_kernel(
    const float* __restrict__ scale_f,
    const float* __restrict__ shift_f,
    float* __restrict__ out) {
    int t = blockIdx.x * blockDim.x + threadIdx.x;
    const int n4 = 3 * H * W / 4;
    if (t >= n4) return;
    float s = scale_f[0], sh = shift_f[0];
    const float4* p0 = (const float4*)g_part[0];
    const float4* p1 = (const float4*)g_part[1];
    const float4* p2 = (const float4*)g_part[2];
    const float4* p3 = (const float4*)g_part[3];
    float4 a = p0[t], b = p1[t], c = p2[t], d = p3[t];
    float4 r;
    r.x = fmaf(((a.x + b.x) + (c.x + d.x)), s, sh);
    r.y = fmaf(((a.y + b.y) + (c.y + d.y)), s, sh);
    r.z = fmaf(((a.z + b.z) + (c.z + d.z)), s, sh);
    r.w = fmaf(((a.w + b.w) + (c.w + d.w)), s, sh);
    ((float4*)out)[t] = r;
}

extern "C" void kernel_launch(void* const* d_in, const int* in_sizes, int n_in,
                              void* d_out, int out_size) {
    const float* xyz     = (const float*)d_in[0];
    const float* chol    = (const float*)d_in[1];
    const float* colors  = (const float*)d_in[2];
    const float* opacity = (const float*)d_in[3];
    const float* scale_f = (const float*)d_in[4];
    const float* shift_f = (const float*)d_in[5];
    float* out = (float*)d_out;

    prep_kernel<<<(NG + 63) / 64, 64>>>(xyz, chol, colors, opacity);
    bin_kernel<<<dim3(SEGS, TY), 256>>>();
    render_kernel<<<dim3(TX, TY, ZSPLIT), 256>>>();
    finish_kernel<<<(3 * H * W / 4 + 255) / 256, 256>>>(scale_f, shift_f, out);
}